// round 4
// baseline (speedup 1.0000x reference)
#include <cuda_runtime.h>
#include <cuda_bf16.h>
#include <cstdint>

#define D 256
#define SS 20000
#define CAP 64   // max rows cached in smem per segment (Binomial(500k,1/20k) tail ~ 55)

// ---- scratch (device globals; allocation is forbidden) ----
__device__ float g_pooled[(size_t)SS * D];   // 20.48 MB
__device__ float g_gsum[SS];
__device__ int   g_segstart[SS + 1];

// ---------------------------------------------------------------------------
// Kernel 1: segment offsets from sorted index. seg_start[s] = lower_bound(index, s)
// ---------------------------------------------------------------------------
__global__ void seg_offsets_kernel(const int* __restrict__ index, int n) {
    int i = blockIdx.x * blockDim.x + threadIdx.x;
    if (i >= n) return;
    int cur = index[i];
    if (i == 0) {
        for (int s = 0; s <= cur; ++s) g_segstart[s] = 0;
    } else {
        int prev = index[i - 1];
        if (prev != cur)
            for (int s = prev + 1; s <= cur; ++s) g_segstart[s] = i;
    }
    if (i == n - 1) {
        for (int s = cur + 1; s <= SS; ++s) g_segstart[s] = n;
    }
}

// ---------------------------------------------------------------------------
// Kernel 2: per-segment softmax-weighted pooling.
// One block (256 threads) per segment. Rows cached in dynamic smem (single
// HBM read of x). Outputs pooled[s][0:256] and gsum[s] = sum of norm. gates.
// ---------------------------------------------------------------------------
__global__ void __launch_bounds__(256) pool_kernel(
    const float* __restrict__ x, const float* __restrict__ w,
    const float* __restrict__ Wg, const float* __restrict__ bg,
    const float* __restrict__ p)
{
    extern __shared__ float sm[];       // CAP*256 floats: row cache (main) / logits (fallback)
    __shared__ float s_wg[D];
    __shared__ float s_logit[CAP];
    __shared__ float s_red[8];
    __shared__ float s_bcast[2];

    const int s   = blockIdx.x;
    const int tid = threadIdx.x;
    const int warp = tid >> 5, lane = tid & 31;

    const int lo = g_segstart[s];
    const int hi = g_segstart[s + 1];
    const int cnt = hi - lo;

    if (cnt == 0) {
        g_pooled[(size_t)s * D + tid] = 0.f;
        if (tid == 0) g_gsum[s] = 0.f;
        return;
    }

    s_wg[tid] = Wg[tid];
    const float bgv = bg[0];
    const float pv  = p[0];
    __syncthreads();

    if (cnt <= CAP) {
        // ---- load segment rows into smem (vectorized, coalesced) ----
        const float4* xin = reinterpret_cast<const float4*>(x + (size_t)lo * D);
        float4* sm4 = reinterpret_cast<float4*>(sm);
        const int nv = cnt * (D / 4);
        for (int v = tid; v < nv; v += 256) sm4[v] = xin[v];
        __syncthreads();

        // ---- logits: one warp per row ----
        for (int r = warp; r < cnt; r += 8) {
            const float* row = sm + r * D;
            float acc = 0.f;
            #pragma unroll
            for (int j = 0; j < 8; ++j)
                acc = fmaf(row[lane + 32 * j], s_wg[lane + 32 * j], acc);
            #pragma unroll
            for (int o = 16; o; o >>= 1) acc += __shfl_xor_sync(0xffffffffu, acc, o);
            if (lane == 0) s_logit[r] = acc + bgv;
        }
        __syncthreads();

        // ---- segment max (warp 0) ----
        if (warp == 0) {
            float m = -3.4e38f;
            for (int r = lane; r < cnt; r += 32) m = fmaxf(m, s_logit[r]);
            #pragma unroll
            for (int o = 16; o; o >>= 1) m = fmaxf(m, __shfl_xor_sync(0xffffffffu, m, o));
            if (lane == 0) s_bcast[0] = m;
        }
        __syncthreads();
        const float mx = s_bcast[0];

        // ---- e = w^p * exp(g - mx) = exp(p*ln w + g - mx) ----
        if (tid < cnt) {
            float wv = w[lo + tid];
            s_logit[tid] = __expf(fmaf(pv, __logf(wv), s_logit[tid] - mx));
        }
        __syncthreads();

        // ---- denom (warp 0) ----
        if (warp == 0) {
            float sum = 0.f;
            for (int r = lane; r < cnt; r += 32) sum += s_logit[r];
            #pragma unroll
            for (int o = 16; o; o >>= 1) sum += __shfl_xor_sync(0xffffffffu, sum, o);
            if (lane == 0) {
                float inv = 1.f / (sum + 1e-10f);
                s_bcast[0] = inv;
                s_bcast[1] = sum * inv;   // sum of normalized gates
            }
        }
        __syncthreads();
        const float inv = s_bcast[0];
        if (tid < cnt) s_logit[tid] *= inv;
        __syncthreads();

        // ---- weighted accumulate: thread = feature column ----
        float acc = 0.f;
        for (int r = 0; r < cnt; ++r)
            acc = fmaf(s_logit[r], sm[r * D + tid], acc);
        g_pooled[(size_t)s * D + tid] = acc;
        if (tid == 0) g_gsum[s] = s_bcast[1];
    } else {
        // ---- fallback: segment too large for smem cache; logits in sm[] ----
        for (int r = warp; r < cnt; r += 8) {
            const float* row = x + (size_t)(lo + r) * D;
            float acc = 0.f;
            #pragma unroll
            for (int j = 0; j < 8; ++j)
                acc = fmaf(row[lane + 32 * j], s_wg[lane + 32 * j], acc);
            #pragma unroll
            for (int o = 16; o; o >>= 1) acc += __shfl_xor_sync(0xffffffffu, acc, o);
            if (lane == 0) sm[r] = acc + bgv;
        }
        __syncthreads();

        // block max
        float m = -3.4e38f;
        for (int r = tid; r < cnt; r += 256) m = fmaxf(m, sm[r]);
        #pragma unroll
        for (int o = 16; o; o >>= 1) m = fmaxf(m, __shfl_xor_sync(0xffffffffu, m, o));
        if (lane == 0) s_red[warp] = m;
        __syncthreads();
        if (warp == 0) {
            float mm = (lane < 8) ? s_red[lane] : -3.4e38f;
            #pragma unroll
            for (int o = 4; o; o >>= 1) mm = fmaxf(mm, __shfl_xor_sync(0xffffffffu, mm, o));
            if (lane == 0) s_bcast[0] = mm;
        }
        __syncthreads();
        const float mx = s_bcast[0];

        float sum = 0.f;
        for (int r = tid; r < cnt; r += 256) {
            float e = __expf(fmaf(pv, __logf(w[lo + r]), sm[r] - mx));
            sm[r] = e;
            sum += e;
        }
        #pragma unroll
        for (int o = 16; o; o >>= 1) sum += __shfl_xor_sync(0xffffffffu, sum, o);
        if (lane == 0) s_red[warp] = sum;
        __syncthreads();
        if (warp == 0) {
            float ss = (lane < 8) ? s_red[lane] : 0.f;
            #pragma unroll
            for (int o = 4; o; o >>= 1) ss += __shfl_xor_sync(0xffffffffu, ss, o);
            if (lane == 0) {
                float inv = 1.f / (ss + 1e-10f);
                s_bcast[0] = inv;
                s_bcast[1] = ss * inv;
            }
        }
        __syncthreads();
        const float inv = s_bcast[0];
        for (int r = tid; r < cnt; r += 256) sm[r] *= inv;
        __syncthreads();

        float acc = 0.f;
        for (int r = 0; r < cnt; ++r)
            acc = fmaf(sm[r], x[(size_t)(lo + r) * D + tid], acc);
        g_pooled[(size_t)s * D + tid] = acc;
        if (tid == 0) g_gsum[s] = s_bcast[1];
    }
}

// ---------------------------------------------------------------------------
// Kernel 3: out = pooled @ Wm + gsum[:,None]*bm[None,:]   (M=20000, N=256, K=256)
// 64x64 block tile, BK=16, 4x4 register micro-tile, 256 threads.
// ---------------------------------------------------------------------------
#define BM 64
#define BN 64
#define BK 16

__global__ void __launch_bounds__(256) gemm_kernel(
    const float* __restrict__ Wm, const float* __restrict__ bm,
    float* __restrict__ out)
{
    __shared__ float As[BK][BM];
    __shared__ float Bs[BK][BN];

    const int m0 = blockIdx.y * BM;
    const int n0 = blockIdx.x * BN;
    const int t  = threadIdx.x;
    const int tx = t & 15;     // 0..15 -> 4 cols each
    const int ty = t >> 4;     // 0..15 -> 4 rows each

    const int la_m = t >> 2;           // 0..63
    const int la_k = (t & 3) * 4;      // 0,4,8,12
    const int lb_k = t >> 4;           // 0..15
    const int lb_n = (t & 15) * 4;     // 0..60

    float acc[4][4] = {};

    for (int k0 = 0; k0 < D; k0 += BK) {
        float4 av = make_float4(0.f, 0.f, 0.f, 0.f);
        const int gm = m0 + la_m;
        if (gm < SS)
            av = *reinterpret_cast<const float4*>(&g_pooled[(size_t)gm * D + k0 + la_k]);
        As[la_k + 0][la_m] = av.x;
        As[la_k + 1][la_m] = av.y;
        As[la_k + 2][la_m] = av.z;
        As[la_k + 3][la_m] = av.w;

        const float4 bv = *reinterpret_cast<const float4*>(
            &Wm[(size_t)(k0 + lb_k) * D + n0 + lb_n]);
        *reinterpret_cast<float4*>(&Bs[lb_k][lb_n]) = bv;
        __syncthreads();

        #pragma unroll
        for (int k = 0; k < BK; ++k) {
            float a[4], b[4];
            #pragma unroll
            for (int i = 0; i < 4; ++i) a[i] = As[k][ty * 4 + i];
            #pragma unroll
            for (int j = 0; j < 4; ++j) b[j] = Bs[k][tx * 4 + j];
            #pragma unroll
            for (int i = 0; i < 4; ++i)
                #pragma unroll
                for (int j = 0; j < 4; ++j)
                    acc[i][j] = fmaf(a[i], b[j], acc[i][j]);
        }
        __syncthreads();
    }

    #pragma unroll
    for (int i = 0; i < 4; ++i) {
        const int m = m0 + ty * 4 + i;
        if (m >= SS) break;
        const float gs = g_gsum[m];
        float4 o;
        o.x = acc[i][0] + gs * bm[n0 + tx * 4 + 0];
        o.y = acc[i][1] + gs * bm[n0 + tx * 4 + 1];
        o.z = acc[i][2] + gs * bm[n0 + tx * 4 + 2];
        o.w = acc[i][3] + gs * bm[n0 + tx * 4 + 3];
        *reinterpret_cast<float4*>(&out[(size_t)m * D + n0 + tx * 4]) = o;
    }
}

// ---------------------------------------------------------------------------
extern "C" void kernel_launch(void* const* d_in, const int* in_sizes, int n_in,
                              void* d_out, int out_size)
{
    const float* x   = (const float*)d_in[0];
    const float* w   = (const float*)d_in[1];
    const float* Wg  = (const float*)d_in[2];
    const float* bg  = (const float*)d_in[3];
    const float* Wm  = (const float*)d_in[4];
    const float* bm  = (const float*)d_in[5];
    const float* p   = (const float*)d_in[6];
    const int*   idx = (const int*)d_in[7];
    float* out = (float*)d_out;

    const int n = in_sizes[0] / D;   // 500000

    // dynamic smem: CAP rows * 256 floats = 64 KB (opt-in > 48 KB)
    static_assert(CAP * D * sizeof(float) == 65536, "smem size");
    cudaFuncSetAttribute(pool_kernel, cudaFuncAttributeMaxDynamicSharedMemorySize,
                         CAP * D * (int)sizeof(float));

    seg_offsets_kernel<<<(n + 255) / 256, 256>>>(idx, n);
    pool_kernel<<<SS, 256, CAP * D * sizeof(float)>>>(x, w, Wg, bg, p);
    gemm_kernel<<<dim3(D / BN, (SS + BM - 1) / BM), 256>>>(Wm, bm, out);
}

// round 5
// speedup vs baseline: 1.1554x; 1.1554x over previous
#include <cuda_runtime.h>
#include <cuda_bf16.h>
#include <cstdint>

#define D 256
#define SS 20000
#define CAP 48   // rows cached in smem per segment; P(cnt>48)~2e-6 for Poisson(25)

// ---- scratch (device globals; allocation is forbidden) ----
__device__ float g_pooled[(size_t)SS * D];   // 20.48 MB
__device__ float g_gsum[SS];
__device__ int   g_segstart[SS + 1];

// ---------------------------------------------------------------------------
// Kernel 1: segment offsets from sorted index. seg_start[s] = lower_bound(index, s)
// ---------------------------------------------------------------------------
__global__ void seg_offsets_kernel(const int* __restrict__ index, int n) {
    int i = blockIdx.x * blockDim.x + threadIdx.x;
    if (i >= n) return;
    int cur = index[i];
    if (i == 0) {
        for (int s = 0; s <= cur; ++s) g_segstart[s] = 0;
    } else {
        int prev = index[i - 1];
        if (prev != cur)
            for (int s = prev + 1; s <= cur; ++s) g_segstart[s] = i;
    }
    if (i == n - 1) {
        for (int s = cur + 1; s <= SS; ++s) g_segstart[s] = n;
    }
}

// ---------------------------------------------------------------------------
// Kernel 2: per-segment softmax-weighted pooling.
// One block (256 threads) per segment. Rows cached in 48KB dynamic smem
// (single HBM read of x) -> 4 CTAs/SM. Outputs pooled[s][:], gsum[s].
// ---------------------------------------------------------------------------
__global__ void __launch_bounds__(256) pool_kernel(
    const float* __restrict__ x, const float* __restrict__ w,
    const float* __restrict__ Wg, const float* __restrict__ bg,
    const float* __restrict__ p)
{
    extern __shared__ float sm[];       // CAP*256 floats: row cache / fallback logits
    __shared__ float s_wg[D];
    __shared__ float s_logit[CAP];
    __shared__ float s_red[8];
    __shared__ float s_bcast[2];

    const int s   = blockIdx.x;
    const int tid = threadIdx.x;
    const int warp = tid >> 5, lane = tid & 31;

    const int lo = g_segstart[s];
    const int hi = g_segstart[s + 1];
    const int cnt = hi - lo;

    if (cnt == 0) {
        g_pooled[(size_t)s * D + tid] = 0.f;
        if (tid == 0) g_gsum[s] = 0.f;
        return;
    }

    s_wg[tid] = Wg[tid];
    const float bgv = bg[0];
    const float pv  = p[0];
    __syncthreads();

    if (cnt <= CAP) {
        // ---- load segment rows into smem (vectorized, coalesced) ----
        const float4* xin = reinterpret_cast<const float4*>(x + (size_t)lo * D);
        float4* sm4 = reinterpret_cast<float4*>(sm);
        const int nv = cnt * (D / 4);
        for (int v = tid; v < nv; v += 256) sm4[v] = xin[v];
        __syncthreads();

        // ---- logits: one warp per row ----
        for (int r = warp; r < cnt; r += 8) {
            const float* row = sm + r * D;
            float acc = 0.f;
            #pragma unroll
            for (int j = 0; j < 8; ++j)
                acc = fmaf(row[lane + 32 * j], s_wg[lane + 32 * j], acc);
            #pragma unroll
            for (int o = 16; o; o >>= 1) acc += __shfl_xor_sync(0xffffffffu, acc, o);
            if (lane == 0) s_logit[r] = acc + bgv;
        }
        __syncthreads();

        // ---- segment max (warp 0) ----
        if (warp == 0) {
            float m = -3.4e38f;
            for (int r = lane; r < cnt; r += 32) m = fmaxf(m, s_logit[r]);
            #pragma unroll
            for (int o = 16; o; o >>= 1) m = fmaxf(m, __shfl_xor_sync(0xffffffffu, m, o));
            if (lane == 0) s_bcast[0] = m;
        }
        __syncthreads();
        const float mx = s_bcast[0];

        // ---- e = w^p * exp(g - mx) = exp(p*ln w + g - mx) ----
        if (tid < cnt) {
            float wv = w[lo + tid];
            s_logit[tid] = __expf(fmaf(pv, __logf(wv), s_logit[tid] - mx));
        }
        __syncthreads();

        // ---- denom (warp 0) ----
        if (warp == 0) {
            float sum = 0.f;
            for (int r = lane; r < cnt; r += 32) sum += s_logit[r];
            #pragma unroll
            for (int o = 16; o; o >>= 1) sum += __shfl_xor_sync(0xffffffffu, sum, o);
            if (lane == 0) {
                float inv = 1.f / (sum + 1e-10f);
                s_bcast[0] = inv;
                s_bcast[1] = sum * inv;   // sum of normalized gates
            }
        }
        __syncthreads();
        const float inv = s_bcast[0];
        if (tid < cnt) s_logit[tid] *= inv;
        __syncthreads();

        // ---- weighted accumulate: thread = feature column ----
        float acc = 0.f;
        for (int r = 0; r < cnt; ++r)
            acc = fmaf(s_logit[r], sm[r * D + tid], acc);
        g_pooled[(size_t)s * D + tid] = acc;
        if (tid == 0) g_gsum[s] = s_bcast[1];
    } else {
        // ---- fallback: segment too large for smem cache; logits in sm[] ----
        for (int r = warp; r < cnt; r += 8) {
            const float* row = x + (size_t)(lo + r) * D;
            float acc = 0.f;
            #pragma unroll
            for (int j = 0; j < 8; ++j)
                acc = fmaf(row[lane + 32 * j], s_wg[lane + 32 * j], acc);
            #pragma unroll
            for (int o = 16; o; o >>= 1) acc += __shfl_xor_sync(0xffffffffu, acc, o);
            if (lane == 0) sm[r] = acc + bgv;
        }
        __syncthreads();

        // block max
        float m = -3.4e38f;
        for (int r = tid; r < cnt; r += 256) m = fmaxf(m, sm[r]);
        #pragma unroll
        for (int o = 16; o; o >>= 1) m = fmaxf(m, __shfl_xor_sync(0xffffffffu, m, o));
        if (lane == 0) s_red[warp] = m;
        __syncthreads();
        if (warp == 0) {
            float mm = (lane < 8) ? s_red[lane] : -3.4e38f;
            #pragma unroll
            for (int o = 4; o; o >>= 1) mm = fmaxf(mm, __shfl_xor_sync(0xffffffffu, mm, o));
            if (lane == 0) s_bcast[0] = mm;
        }
        __syncthreads();
        const float mx = s_bcast[0];

        float sum = 0.f;
        for (int r = tid; r < cnt; r += 256) {
            float e = __expf(fmaf(pv, __logf(w[lo + r]), sm[r] - mx));
            sm[r] = e;
            sum += e;
        }
        #pragma unroll
        for (int o = 16; o; o >>= 1) sum += __shfl_xor_sync(0xffffffffu, sum, o);
        if (lane == 0) s_red[warp] = sum;
        __syncthreads();
        if (warp == 0) {
            float ss = (lane < 8) ? s_red[lane] : 0.f;
            #pragma unroll
            for (int o = 4; o; o >>= 1) ss += __shfl_xor_sync(0xffffffffu, ss, o);
            if (lane == 0) {
                float inv = 1.f / (ss + 1e-10f);
                s_bcast[0] = inv;
                s_bcast[1] = ss * inv;
            }
        }
        __syncthreads();
        const float inv = s_bcast[0];
        for (int r = tid; r < cnt; r += 256) sm[r] *= inv;
        __syncthreads();

        float acc = 0.f;
        for (int r = 0; r < cnt; ++r)
            acc = fmaf(sm[r], x[(size_t)(lo + r) * D + tid], acc);
        g_pooled[(size_t)s * D + tid] = acc;
        if (tid == 0) g_gsum[s] = s_bcast[1];
    }
}

// ---------------------------------------------------------------------------
// Kernel 3: out = pooled @ Wm + gsum[:,None]*bm[None,:]   (M=20000, N=256, K=256)
// 128x128 block tile, BK=8, 8x8 register micro-tile, 256 threads,
// double-buffered smem + register prefetch. FMA-bound by design.
// ---------------------------------------------------------------------------
#define GBM 128
#define GBN 128
#define GBK 8

__global__ void __launch_bounds__(256) gemm_kernel(
    const float* __restrict__ Wm, const float* __restrict__ bm,
    float* __restrict__ out)
{
    __shared__ float As[2][GBK][GBM];
    __shared__ float Bs[2][GBK][GBN];

    const int m0 = blockIdx.y * GBM;
    const int n0 = blockIdx.x * GBN;
    const int t  = threadIdx.x;

    // global->smem load mapping
    const int a_row = t >> 1;          // 0..127
    const int a_k   = (t & 1) * 4;     // 0 or 4
    const int b_k   = t >> 5;          // 0..7
    const int b_n   = (t & 31) * 4;    // 0..124

    // compute mapping: 16x16 threads, each 8x8
    const int tx = t & 15;
    const int ty = t >> 4;

    float acc[8][8] = {};

    // ---- prologue: load tile 0 ----
    {
        const int gm = m0 + a_row;
        float4 av = make_float4(0.f, 0.f, 0.f, 0.f);
        if (gm < SS)
            av = *reinterpret_cast<const float4*>(&g_pooled[(size_t)gm * D + a_k]);
        As[0][a_k + 0][a_row] = av.x;
        As[0][a_k + 1][a_row] = av.y;
        As[0][a_k + 2][a_row] = av.z;
        As[0][a_k + 3][a_row] = av.w;
        const float4 bv = *reinterpret_cast<const float4*>(
            &Wm[(size_t)b_k * D + n0 + b_n]);
        *reinterpret_cast<float4*>(&Bs[0][b_k][b_n]) = bv;
    }
    __syncthreads();

    int buf = 0;
    for (int k0 = 0; k0 < D; k0 += GBK) {
        // ---- register prefetch of next tile (overlaps with compute) ----
        float4 av = make_float4(0.f, 0.f, 0.f, 0.f), bv;
        const bool has_next = (k0 + GBK) < D;
        if (has_next) {
            const int gm = m0 + a_row;
            if (gm < SS)
                av = *reinterpret_cast<const float4*>(
                    &g_pooled[(size_t)gm * D + k0 + GBK + a_k]);
            bv = *reinterpret_cast<const float4*>(
                &Wm[(size_t)(k0 + GBK + b_k) * D + n0 + b_n]);
        }

        // ---- compute on current buffer ----
        #pragma unroll
        for (int k = 0; k < GBK; ++k) {
            float a[8], b[8];
            *reinterpret_cast<float4*>(&a[0]) =
                *reinterpret_cast<const float4*>(&As[buf][k][ty * 8]);
            *reinterpret_cast<float4*>(&a[4]) =
                *reinterpret_cast<const float4*>(&As[buf][k][ty * 8 + 4]);
            *reinterpret_cast<float4*>(&b[0]) =
                *reinterpret_cast<const float4*>(&Bs[buf][k][tx * 8]);
            *reinterpret_cast<float4*>(&b[4]) =
                *reinterpret_cast<const float4*>(&Bs[buf][k][tx * 8 + 4]);
            #pragma unroll
            for (int i = 0; i < 8; ++i)
                #pragma unroll
                for (int j = 0; j < 8; ++j)
                    acc[i][j] = fmaf(a[i], b[j], acc[i][j]);
        }

        if (has_next) {
            const int nb = buf ^ 1;
            As[nb][a_k + 0][a_row] = av.x;
            As[nb][a_k + 1][a_row] = av.y;
            As[nb][a_k + 2][a_row] = av.z;
            As[nb][a_k + 3][a_row] = av.w;
            *reinterpret_cast<float4*>(&Bs[nb][b_k][b_n]) = bv;
            __syncthreads();
            buf = nb;
        }
    }

    // ---- epilogue: + gsum[m]*bm[n], vectorized stores ----
    float bmr[8];
    *reinterpret_cast<float4*>(&bmr[0]) =
        *reinterpret_cast<const float4*>(&bm[n0 + tx * 8]);
    *reinterpret_cast<float4*>(&bmr[4]) =
        *reinterpret_cast<const float4*>(&bm[n0 + tx * 8 + 4]);

    #pragma unroll
    for (int i = 0; i < 8; ++i) {
        const int m = m0 + ty * 8 + i;
        if (m >= SS) break;
        const float gs = g_gsum[m];
        float4 o0, o1;
        o0.x = fmaf(gs, bmr[0], acc[i][0]);
        o0.y = fmaf(gs, bmr[1], acc[i][1]);
        o0.z = fmaf(gs, bmr[2], acc[i][2]);
        o0.w = fmaf(gs, bmr[3], acc[i][3]);
        o1.x = fmaf(gs, bmr[4], acc[i][4]);
        o1.y = fmaf(gs, bmr[5], acc[i][5]);
        o1.z = fmaf(gs, bmr[6], acc[i][6]);
        o1.w = fmaf(gs, bmr[7], acc[i][7]);
        *reinterpret_cast<float4*>(&out[(size_t)m * D + n0 + tx * 8])     = o0;
        *reinterpret_cast<float4*>(&out[(size_t)m * D + n0 + tx * 8 + 4]) = o1;
    }
}

// ---------------------------------------------------------------------------
extern "C" void kernel_launch(void* const* d_in, const int* in_sizes, int n_in,
                              void* d_out, int out_size)
{
    const float* x   = (const float*)d_in[0];
    const float* w   = (const float*)d_in[1];
    const float* Wg  = (const float*)d_in[2];
    const float* bg  = (const float*)d_in[3];
    const float* Wm  = (const float*)d_in[4];
    const float* bm  = (const float*)d_in[5];
    const float* p   = (const float*)d_in[6];
    const int*   idx = (const int*)d_in[7];
    float* out = (float*)d_out;

    const int n = in_sizes[0] / D;   // 500000

    cudaFuncSetAttribute(pool_kernel, cudaFuncAttributeMaxDynamicSharedMemorySize,
                         CAP * D * (int)sizeof(float));

    seg_offsets_kernel<<<(n + 255) / 256, 256>>>(idx, n);
    pool_kernel<<<SS, 256, CAP * D * sizeof(float)>>>(x, w, Wg, bg, p);
    gemm_kernel<<<dim3(D / GBN, (SS + GBM - 1) / GBM), 256>>>(Wm, bm, out);
}

// round 9
// speedup vs baseline: 1.2934x; 1.1194x over previous
#include <cuda_runtime.h>
#include <cuda_bf16.h>
#include <cstdint>

#define D 256
#define SS 20000
#define CAP 34   // rows cached in smem; 34KB dynamic -> 6 CTAs/SM. P(cnt>34|Poisson25)~3% -> fallback

// ---- scratch (device globals; allocation is forbidden) ----
__device__ float g_pooled[(size_t)SS * D];   // 20.48 MB
__device__ float g_gsum[SS];
__device__ int   g_segstart[SS + 1];

// ---------------------------------------------------------------------------
// Kernel 1: segment offsets from sorted index. seg_start[s] = lower_bound(index, s)
// ---------------------------------------------------------------------------
__global__ void seg_offsets_kernel(const int* __restrict__ index, int n) {
    int i = blockIdx.x * blockDim.x + threadIdx.x;
    if (i >= n) return;
    int cur = index[i];
    if (i == 0) {
        for (int s = 0; s <= cur; ++s) g_segstart[s] = 0;
    } else {
        int prev = index[i - 1];
        if (prev != cur)
            for (int s = prev + 1; s <= cur; ++s) g_segstart[s] = i;
    }
    if (i == n - 1) {
        for (int s = cur + 1; s <= SS; ++s) g_segstart[s] = n;
    }
}

// ---------------------------------------------------------------------------
// Kernel 2: per-segment softmax-weighted pooling.
// One block (256 threads) per segment. Rows cached in 34KB dynamic smem
// (single HBM read of x) -> 6 CTAs/SM. Outputs pooled[s][:], gsum[s].
// ---------------------------------------------------------------------------
__global__ void __launch_bounds__(256) pool_kernel(
    const float* __restrict__ x, const float* __restrict__ w,
    const float* __restrict__ Wg, const float* __restrict__ bg,
    const float* __restrict__ p)
{
    extern __shared__ float sm[];       // CAP*256 floats: row cache / fallback logits
    __shared__ float s_wg[D];
    __shared__ float s_logit[CAP];
    __shared__ float s_red[8];
    __shared__ float s_bcast[2];

    const int s   = blockIdx.x;
    const int tid = threadIdx.x;
    const int warp = tid >> 5, lane = tid & 31;

    const int lo = g_segstart[s];
    const int hi = g_segstart[s + 1];
    const int cnt = hi - lo;

    if (cnt == 0) {
        g_pooled[(size_t)s * D + tid] = 0.f;
        if (tid == 0) g_gsum[s] = 0.f;
        return;
    }

    s_wg[tid] = Wg[tid];
    const float bgv = bg[0];
    const float pv  = p[0];
    __syncthreads();

    if (cnt <= CAP) {
        // ---- load segment rows into smem (vectorized, coalesced) ----
        const float4* xin = reinterpret_cast<const float4*>(x + (size_t)lo * D);
        float4* sm4 = reinterpret_cast<float4*>(sm);
        const int nv = cnt * (D / 4);
        for (int v = tid; v < nv; v += 256) sm4[v] = xin[v];
        __syncthreads();

        // ---- logits: one warp per row ----
        for (int r = warp; r < cnt; r += 8) {
            const float* row = sm + r * D;
            float acc = 0.f;
            #pragma unroll
            for (int j = 0; j < 8; ++j)
                acc = fmaf(row[lane + 32 * j], s_wg[lane + 32 * j], acc);
            #pragma unroll
            for (int o = 16; o; o >>= 1) acc += __shfl_xor_sync(0xffffffffu, acc, o);
            if (lane == 0) s_logit[r] = acc + bgv;
        }
        __syncthreads();

        // ---- segment max (warp 0) ----
        if (warp == 0) {
            float m = -3.4e38f;
            for (int r = lane; r < cnt; r += 32) m = fmaxf(m, s_logit[r]);
            #pragma unroll
            for (int o = 16; o; o >>= 1) m = fmaxf(m, __shfl_xor_sync(0xffffffffu, m, o));
            if (lane == 0) s_bcast[0] = m;
        }
        __syncthreads();
        const float mx = s_bcast[0];

        // ---- e = w^p * exp(g - mx) = exp(p*ln w + g - mx) ----
        if (tid < cnt) {
            float wv = w[lo + tid];
            s_logit[tid] = __expf(fmaf(pv, __logf(wv), s_logit[tid] - mx));
        }
        __syncthreads();

        // ---- denom (warp 0) ----
        if (warp == 0) {
            float sum = 0.f;
            for (int r = lane; r < cnt; r += 32) sum += s_logit[r];
            #pragma unroll
            for (int o = 16; o; o >>= 1) sum += __shfl_xor_sync(0xffffffffu, sum, o);
            if (lane == 0) {
                float inv = 1.f / (sum + 1e-10f);
                s_bcast[0] = inv;
                s_bcast[1] = sum * inv;   // sum of normalized gates
            }
        }
        __syncthreads();
        const float inv = s_bcast[0];
        if (tid < cnt) s_logit[tid] *= inv;
        __syncthreads();

        // ---- weighted accumulate: thread = feature column ----
        float acc = 0.f;
        for (int r = 0; r < cnt; ++r)
            acc = fmaf(s_logit[r], sm[r * D + tid], acc);
        g_pooled[(size_t)s * D + tid] = acc;
        if (tid == 0) g_gsum[s] = s_bcast[1];
    } else {
        // ---- fallback: segment too large for smem cache; logits in sm[] ----
        for (int r = warp; r < cnt; r += 8) {
            const float* row = x + (size_t)(lo + r) * D;
            float acc = 0.f;
            #pragma unroll
            for (int j = 0; j < 8; ++j)
                acc = fmaf(row[lane + 32 * j], s_wg[lane + 32 * j], acc);
            #pragma unroll
            for (int o = 16; o; o >>= 1) acc += __shfl_xor_sync(0xffffffffu, acc, o);
            if (lane == 0) sm[r] = acc + bgv;
        }
        __syncthreads();

        // block max
        float m = -3.4e38f;
        for (int r = tid; r < cnt; r += 256) m = fmaxf(m, sm[r]);
        #pragma unroll
        for (int o = 16; o; o >>= 1) m = fmaxf(m, __shfl_xor_sync(0xffffffffu, m, o));
        if (lane == 0) s_red[warp] = m;
        __syncthreads();
        if (warp == 0) {
            float mm = (lane < 8) ? s_red[lane] : -3.4e38f;
            #pragma unroll
            for (int o = 4; o; o >>= 1) mm = fmaxf(mm, __shfl_xor_sync(0xffffffffu, mm, o));
            if (lane == 0) s_bcast[0] = mm;
        }
        __syncthreads();
        const float mx = s_bcast[0];

        float sum = 0.f;
        for (int r = tid; r < cnt; r += 256) {
            float e = __expf(fmaf(pv, __logf(w[lo + r]), sm[r] - mx));
            sm[r] = e;
            sum += e;
        }
        #pragma unroll
        for (int o = 16; o; o >>= 1) sum += __shfl_xor_sync(0xffffffffu, sum, o);
        if (lane == 0) s_red[warp] = sum;
        __syncthreads();
        if (warp == 0) {
            float ss = (lane < 8) ? s_red[lane] : 0.f;
            #pragma unroll
            for (int o = 4; o; o >>= 1) ss += __shfl_xor_sync(0xffffffffu, ss, o);
            if (lane == 0) {
                float inv = 1.f / (ss + 1e-10f);
                s_bcast[0] = inv;
                s_bcast[1] = ss * inv;
            }
        }
        __syncthreads();
        const float inv = s_bcast[0];
        for (int r = tid; r < cnt; r += 256) sm[r] *= inv;
        __syncthreads();

        float acc = 0.f;
        for (int r = 0; r < cnt; ++r)
            acc = fmaf(sm[r], x[(size_t)(lo + r) * D + tid], acc);
        g_pooled[(size_t)s * D + tid] = acc;
        if (tid == 0) g_gsum[s] = s_bcast[1];
    }
}

// ---------------------------------------------------------------------------
// Kernel 3: out = pooled @ Wm + gsum[:,None]*bm[None,:]   (M=20000, N=256, K=256)
// 128x128 block tile, BK=8, 8x8 micro-tile with PACKED fma.rn.f32x2
// (2x fp32 MAC throughput vs scalar FFMA), double-buffered smem.
// ---------------------------------------------------------------------------
#define GBM 128
#define GBN 128
#define GBK 8

#define FMA_F32X2(acc, a, b) \
    asm("fma.rn.f32x2 %0, %1, %2, %3;" : "=l"(acc) : "l"(a), "l"(b), "l"(acc))
#define PACK_DUP_F32X2(out, v) \
    asm("mov.b64 %0, {%1, %1};" : "=l"(out) : "r"(__float_as_uint(v)))
#define UNPACK_F32X2(lo, hi, in) \
    asm("mov.b64 {%0, %1}, %2;" : "=r"(lo), "=r"(hi) : "l"(in))

__global__ void __launch_bounds__(256) gemm_kernel(
    const float* __restrict__ Wm, const float* __restrict__ bm,
    float* __restrict__ out)
{
    __shared__ float As[2][GBK][GBM];
    __shared__ float Bs[2][GBK][GBN];

    const int m0 = blockIdx.y * GBM;
    const int n0 = blockIdx.x * GBN;
    const int t  = threadIdx.x;

    // global->smem load mapping
    const int a_row = t >> 1;          // 0..127
    const int a_k   = (t & 1) * 4;     // 0 or 4
    const int b_k   = t >> 5;          // 0..7
    const int b_n   = (t & 31) * 4;    // 0..124

    // compute mapping: 16x16 threads, each 8x8
    const int tx = t & 15;
    const int ty = t >> 4;

    // accumulators: 8 rows x 4 packed f32x2 pairs (= 8x8 floats)
    unsigned long long acc2[8][4];
    #pragma unroll
    for (int i = 0; i < 8; ++i)
        #pragma unroll
        for (int j = 0; j < 4; ++j) acc2[i][j] = 0ull;

    // ---- prologue: load tile 0 ----
    {
        const int gm = m0 + a_row;
        float4 av = make_float4(0.f, 0.f, 0.f, 0.f);
        if (gm < SS)
            av = *reinterpret_cast<const float4*>(&g_pooled[(size_t)gm * D + a_k]);
        As[0][a_k + 0][a_row] = av.x;
        As[0][a_k + 1][a_row] = av.y;
        As[0][a_k + 2][a_row] = av.z;
        As[0][a_k + 3][a_row] = av.w;
        const float4 bv = *reinterpret_cast<const float4*>(
            &Wm[(size_t)b_k * D + n0 + b_n]);
        *reinterpret_cast<float4*>(&Bs[0][b_k][b_n]) = bv;
    }
    __syncthreads();

    int buf = 0;
    for (int k0 = 0; k0 < D; k0 += GBK) {
        // ---- register prefetch of next tile (overlaps with compute) ----
        float4 av = make_float4(0.f, 0.f, 0.f, 0.f), bv;
        const bool has_next = (k0 + GBK) < D;
        if (has_next) {
            const int gm = m0 + a_row;
            if (gm < SS)
                av = *reinterpret_cast<const float4*>(
                    &g_pooled[(size_t)gm * D + k0 + GBK + a_k]);
            bv = *reinterpret_cast<const float4*>(
                &Wm[(size_t)(k0 + GBK + b_k) * D + n0 + b_n]);
        }

        // ---- compute on current buffer (packed f32x2) ----
        #pragma unroll
        for (int k = 0; k < GBK; ++k) {
            float a[8];
            *reinterpret_cast<float4*>(&a[0]) =
                *reinterpret_cast<const float4*>(&As[buf][k][ty * 8]);
            *reinterpret_cast<float4*>(&a[4]) =
                *reinterpret_cast<const float4*>(&As[buf][k][ty * 8 + 4]);
            ulonglong2 bv0 = *reinterpret_cast<const ulonglong2*>(&Bs[buf][k][tx * 8]);
            ulonglong2 bv1 = *reinterpret_cast<const ulonglong2*>(&Bs[buf][k][tx * 8 + 4]);
            unsigned long long b2[4] = {bv0.x, bv0.y, bv1.x, bv1.y};

            unsigned long long a2[8];
            #pragma unroll
            for (int i = 0; i < 8; ++i) PACK_DUP_F32X2(a2[i], a[i]);

            #pragma unroll
            for (int i = 0; i < 8; ++i)
                #pragma unroll
                for (int j = 0; j < 4; ++j)
                    FMA_F32X2(acc2[i][j], a2[i], b2[j]);
        }

        if (has_next) {
            const int nb = buf ^ 1;
            As[nb][a_k + 0][a_row] = av.x;
            As[nb][a_k + 1][a_row] = av.y;
            As[nb][a_k + 2][a_row] = av.z;
            As[nb][a_k + 3][a_row] = av.w;
            *reinterpret_cast<float4*>(&Bs[nb][b_k][b_n]) = bv;
            __syncthreads();
            buf = nb;
        }
    }

    // ---- epilogue: + gsum[m]*bm[n], vectorized stores ----
    float bmr[8];
    *reinterpret_cast<float4*>(&bmr[0]) =
        *reinterpret_cast<const float4*>(&bm[n0 + tx * 8]);
    *reinterpret_cast<float4*>(&bmr[4]) =
        *reinterpret_cast<const float4*>(&bm[n0 + tx * 8 + 4]);

    #pragma unroll
    for (int i = 0; i < 8; ++i) {
        const int m = m0 + ty * 8 + i;
        if (m >= SS) break;
        const float gs = g_gsum[m];
        float accf[8];
        #pragma unroll
        for (int j = 0; j < 4; ++j) {
            unsigned int lo, hi;
            UNPACK_F32X2(lo, hi, acc2[i][j]);
            accf[2 * j]     = __uint_as_float(lo);
            accf[2 * j + 1] = __uint_as_float(hi);
        }
        float4 o0, o1;
        o0.x = fmaf(gs, bmr[0], accf[0]);
        o0.y = fmaf(gs, bmr[1], accf[1]);
        o0.z = fmaf(gs, bmr[2], accf[2]);
        o0.w = fmaf(gs, bmr[3], accf[3]);
        o1.x = fmaf(gs, bmr[4], accf[4]);
        o1.y = fmaf(gs, bmr[5], accf[5]);
        o1.z = fmaf(gs, bmr[6], accf[6]);
        o1.w = fmaf(gs, bmr[7], accf[7]);
        *reinterpret_cast<float4*>(&out[(size_t)m * D + n0 + tx * 8])     = o0;
        *reinterpret_cast<float4*>(&out[(size_t)m * D + n0 + tx * 8 + 4]) = o1;
    }
}

// ---------------------------------------------------------------------------
extern "C" void kernel_launch(void* const* d_in, const int* in_sizes, int n_in,
                              void* d_out, int out_size)
{
    const float* x   = (const float*)d_in[0];
    const float* w   = (const float*)d_in[1];
    const float* Wg  = (const float*)d_in[2];
    const float* bg  = (const float*)d_in[3];
    const float* Wm  = (const float*)d_in[4];
    const float* bm  = (const float*)d_in[5];
    const float* p   = (const float*)d_in[6];
    const int*   idx = (const int*)d_in[7];
    float* out = (float*)d_out;

    const int n = in_sizes[0] / D;   // 500000

    cudaFuncSetAttribute(pool_kernel, cudaFuncAttributeMaxDynamicSharedMemorySize,
                         CAP * D * (int)sizeof(float));

    seg_offsets_kernel<<<(n + 255) / 256, 256>>>(idx, n);
    pool_kernel<<<SS, 256, CAP * D * sizeof(float)>>>(x, w, Wg, bg, p);
    gemm_kernel<<<dim3(D / GBN, (SS + GBM - 1) / GBM), 256>>>(Wm, bm, out);
}

// round 10
// speedup vs baseline: 1.7245x; 1.3333x over previous
#include <cuda_runtime.h>
#include <cuda_bf16.h>
#include <cstdint>

#define D 256
#define SS 20000

// ---- scratch (device globals; allocation is forbidden) ----
__device__ float g_pooled[(size_t)SS * D];   // 20.48 MB
__device__ float g_gsum[SS];
__device__ int   g_segstart[SS + 1];

// ---------------------------------------------------------------------------
// Kernel 1: segment offsets from sorted index. seg_start[s] = lower_bound(index, s)
// ---------------------------------------------------------------------------
__global__ void seg_offsets_kernel(const int* __restrict__ index, int n) {
    int i = blockIdx.x * blockDim.x + threadIdx.x;
    if (i >= n) return;
    int cur = index[i];
    if (i == 0) {
        for (int s = 0; s <= cur; ++s) g_segstart[s] = 0;
    } else {
        int prev = index[i - 1];
        if (prev != cur)
            for (int s = prev + 1; s <= cur; ++s) g_segstart[s] = i;
    }
    if (i == n - 1) {
        for (int s = cur + 1; s <= SS; ++s) g_segstart[s] = n;
    }
}

// ---------------------------------------------------------------------------
// Kernel 2: warp-per-segment online-softmax pooling. Barrier-free, smem-free.
// Lane l owns feature columns [8l, 8l+8). Per row: coalesced warp load,
// partial dot with Wg slice, butterfly-reduced logit, flash-style running
// (max, denom, acc) update. Single pass over x (512 MB) -> HBM-bound.
// ---------------------------------------------------------------------------
__global__ void __launch_bounds__(256) pool_kernel(
    const float* __restrict__ x, const float* __restrict__ w,
    const float* __restrict__ Wg, const float* __restrict__ bg,
    const float* __restrict__ p)
{
    const int warp = threadIdx.x >> 5, lane = threadIdx.x & 31;
    const int s = blockIdx.x * 8 + warp;
    if (s >= SS) return;

    const int lo  = g_segstart[s];
    const int cnt = g_segstart[s + 1] - lo;

    float* outp = g_pooled + (size_t)s * D + lane * 8;

    if (cnt == 0) {
        float4 z = make_float4(0.f, 0.f, 0.f, 0.f);
        *reinterpret_cast<float4*>(outp)     = z;
        *reinterpret_cast<float4*>(outp + 4) = z;
        if (lane == 0) g_gsum[s] = 0.f;
        return;
    }

    // Wg slice for this lane's 8 columns
    const float4 wg0 = *reinterpret_cast<const float4*>(Wg + lane * 8);
    const float4 wg1 = *reinterpret_cast<const float4*>(Wg + lane * 8 + 4);
    const float bgv = bg[0];
    const float pv  = p[0];

    float m = -3.4e38f, dnm = 0.f;
    float acc[8] = {0.f, 0.f, 0.f, 0.f, 0.f, 0.f, 0.f, 0.f};

    const float* base = x + (size_t)lo * D + lane * 8;

    // prefetch row 0
    float4 c0 = *reinterpret_cast<const float4*>(base);
    float4 c1 = *reinterpret_cast<const float4*>(base + 4);
    float  wc = w[lo];

    for (int r = 0; r < cnt; ++r) {
        // ---- prefetch next row (overlaps with compute below) ----
        float4 n0 = c0, n1 = c1;
        float  wn = wc;
        if (r + 1 < cnt) {
            const float* nb = base + (size_t)(r + 1) * D;
            n0 = *reinterpret_cast<const float4*>(nb);
            n1 = *reinterpret_cast<const float4*>(nb + 4);
            wn = w[lo + r + 1];
        }

        // ---- partial dot over this lane's 8 columns ----
        float t;
        t = c0.x * wg0.x;
        t = fmaf(c0.y, wg0.y, t);
        t = fmaf(c0.z, wg0.z, t);
        t = fmaf(c0.w, wg0.w, t);
        t = fmaf(c1.x, wg1.x, t);
        t = fmaf(c1.y, wg1.y, t);
        t = fmaf(c1.z, wg1.z, t);
        t = fmaf(c1.w, wg1.w, t);
        #pragma unroll
        for (int o = 16; o; o >>= 1) t += __shfl_xor_sync(0xffffffffu, t, o);
        const float g = t + bgv;

        // ---- online softmax update (branchless) ----
        const float mn    = fmaxf(m, g);
        const float scale = __expf(m - mn);          // 1 if no new max; 0 on first row
        const float e     = __expf(fmaf(pv, __logf(wc), g - mn));
        dnm = fmaf(dnm, scale, e);
        acc[0] = fmaf(acc[0], scale, e * c0.x);
        acc[1] = fmaf(acc[1], scale, e * c0.y);
        acc[2] = fmaf(acc[2], scale, e * c0.z);
        acc[3] = fmaf(acc[3], scale, e * c0.w);
        acc[4] = fmaf(acc[4], scale, e * c1.x);
        acc[5] = fmaf(acc[5], scale, e * c1.y);
        acc[6] = fmaf(acc[6], scale, e * c1.z);
        acc[7] = fmaf(acc[7], scale, e * c1.w);
        m = mn;

        c0 = n0; c1 = n1; wc = wn;
    }

    const float inv = 1.f / (dnm + 1e-10f);
    float4 o0, o1;
    o0.x = acc[0] * inv; o0.y = acc[1] * inv; o0.z = acc[2] * inv; o0.w = acc[3] * inv;
    o1.x = acc[4] * inv; o1.y = acc[5] * inv; o1.z = acc[6] * inv; o1.w = acc[7] * inv;
    *reinterpret_cast<float4*>(outp)     = o0;
    *reinterpret_cast<float4*>(outp + 4) = o1;
    if (lane == 0) g_gsum[s] = dnm * inv;   // sum of normalized gates
}

// ---------------------------------------------------------------------------
// Kernel 3: out = pooled @ Wm + gsum[:,None]*bm[None,:]   (M=20000, N=256, K=256)
// 128x128 block tile, BK=8, 8x8 micro-tile with PACKED fma.rn.f32x2
// (2x fp32 MAC throughput vs scalar FFMA), double-buffered smem.
// ---------------------------------------------------------------------------
#define GBM 128
#define GBN 128
#define GBK 8

#define FMA_F32X2(acc, a, b) \
    asm("fma.rn.f32x2 %0, %1, %2, %3;" : "=l"(acc) : "l"(a), "l"(b), "l"(acc))
#define PACK_DUP_F32X2(out, v) \
    asm("mov.b64 %0, {%1, %1};" : "=l"(out) : "r"(__float_as_uint(v)))
#define UNPACK_F32X2(lo, hi, in) \
    asm("mov.b64 {%0, %1}, %2;" : "=r"(lo), "=r"(hi) : "l"(in))

__global__ void __launch_bounds__(256) gemm_kernel(
    const float* __restrict__ Wm, const float* __restrict__ bm,
    float* __restrict__ out)
{
    __shared__ float As[2][GBK][GBM];
    __shared__ float Bs[2][GBK][GBN];

    const int m0 = blockIdx.y * GBM;
    const int n0 = blockIdx.x * GBN;
    const int t  = threadIdx.x;

    // global->smem load mapping
    const int a_row = t >> 1;          // 0..127
    const int a_k   = (t & 1) * 4;     // 0 or 4
    const int b_k   = t >> 5;          // 0..7
    const int b_n   = (t & 31) * 4;    // 0..124

    // compute mapping: 16x16 threads, each 8x8
    const int tx = t & 15;
    const int ty = t >> 4;

    // accumulators: 8 rows x 4 packed f32x2 pairs (= 8x8 floats)
    unsigned long long acc2[8][4];
    #pragma unroll
    for (int i = 0; i < 8; ++i)
        #pragma unroll
        for (int j = 0; j < 4; ++j) acc2[i][j] = 0ull;

    // ---- prologue: load tile 0 ----
    {
        const int gm = m0 + a_row;
        float4 av = make_float4(0.f, 0.f, 0.f, 0.f);
        if (gm < SS)
            av = *reinterpret_cast<const float4*>(&g_pooled[(size_t)gm * D + a_k]);
        As[0][a_k + 0][a_row] = av.x;
        As[0][a_k + 1][a_row] = av.y;
        As[0][a_k + 2][a_row] = av.z;
        As[0][a_k + 3][a_row] = av.w;
        const float4 bv = *reinterpret_cast<const float4*>(
            &Wm[(size_t)b_k * D + n0 + b_n]);
        *reinterpret_cast<float4*>(&Bs[0][b_k][b_n]) = bv;
    }
    __syncthreads();

    int buf = 0;
    for (int k0 = 0; k0 < D; k0 += GBK) {
        // ---- register prefetch of next tile (overlaps with compute) ----
        float4 av = make_float4(0.f, 0.f, 0.f, 0.f), bv;
        const bool has_next = (k0 + GBK) < D;
        if (has_next) {
            const int gm = m0 + a_row;
            if (gm < SS)
                av = *reinterpret_cast<const float4*>(
                    &g_pooled[(size_t)gm * D + k0 + GBK + a_k]);
            bv = *reinterpret_cast<const float4*>(
                &Wm[(size_t)(k0 + GBK + b_k) * D + n0 + b_n]);
        }

        // ---- compute on current buffer (packed f32x2) ----
        #pragma unroll
        for (int k = 0; k < GBK; ++k) {
            float a[8];
            *reinterpret_cast<float4*>(&a[0]) =
                *reinterpret_cast<const float4*>(&As[buf][k][ty * 8]);
            *reinterpret_cast<float4*>(&a[4]) =
                *reinterpret_cast<const float4*>(&As[buf][k][ty * 8 + 4]);
            ulonglong2 bv0 = *reinterpret_cast<const ulonglong2*>(&Bs[buf][k][tx * 8]);
            ulonglong2 bv1 = *reinterpret_cast<const ulonglong2*>(&Bs[buf][k][tx * 8 + 4]);
            unsigned long long b2[4] = {bv0.x, bv0.y, bv1.x, bv1.y};

            unsigned long long a2[8];
            #pragma unroll
            for (int i = 0; i < 8; ++i) PACK_DUP_F32X2(a2[i], a[i]);

            #pragma unroll
            for (int i = 0; i < 8; ++i)
                #pragma unroll
                for (int j = 0; j < 4; ++j)
                    FMA_F32X2(acc2[i][j], a2[i], b2[j]);
        }

        if (has_next) {
            const int nb = buf ^ 1;
            As[nb][a_k + 0][a_row] = av.x;
            As[nb][a_k + 1][a_row] = av.y;
            As[nb][a_k + 2][a_row] = av.z;
            As[nb][a_k + 3][a_row] = av.w;
            *reinterpret_cast<float4*>(&Bs[nb][b_k][b_n]) = bv;
            __syncthreads();
            buf = nb;
        }
    }

    // ---- epilogue: + gsum[m]*bm[n], vectorized stores ----
    float bmr[8];
    *reinterpret_cast<float4*>(&bmr[0]) =
        *reinterpret_cast<const float4*>(&bm[n0 + tx * 8]);
    *reinterpret_cast<float4*>(&bmr[4]) =
        *reinterpret_cast<const float4*>(&bm[n0 + tx * 8 + 4]);

    #pragma unroll
    for (int i = 0; i < 8; ++i) {
        const int m = m0 + ty * 8 + i;
        if (m >= SS) break;
        const float gs = g_gsum[m];
        float accf[8];
        #pragma unroll
        for (int j = 0; j < 4; ++j) {
            unsigned int lo, hi;
            UNPACK_F32X2(lo, hi, acc2[i][j]);
            accf[2 * j]     = __uint_as_float(lo);
            accf[2 * j + 1] = __uint_as_float(hi);
        }
        float4 o0, o1;
        o0.x = fmaf(gs, bmr[0], accf[0]);
        o0.y = fmaf(gs, bmr[1], accf[1]);
        o0.z = fmaf(gs, bmr[2], accf[2]);
        o0.w = fmaf(gs, bmr[3], accf[3]);
        o1.x = fmaf(gs, bmr[4], accf[4]);
        o1.y = fmaf(gs, bmr[5], accf[5]);
        o1.z = fmaf(gs, bmr[6], accf[6]);
        o1.w = fmaf(gs, bmr[7], accf[7]);
        *reinterpret_cast<float4*>(&out[(size_t)m * D + n0 + tx * 8])     = o0;
        *reinterpret_cast<float4*>(&out[(size_t)m * D + n0 + tx * 8 + 4]) = o1;
    }
}

// ---------------------------------------------------------------------------
extern "C" void kernel_launch(void* const* d_in, const int* in_sizes, int n_in,
                              void* d_out, int out_size)
{
    const float* x   = (const float*)d_in[0];
    const float* w   = (const float*)d_in[1];
    const float* Wg  = (const float*)d_in[2];
    const float* bg  = (const float*)d_in[3];
    const float* Wm  = (const float*)d_in[4];
    const float* bm  = (const float*)d_in[5];
    const float* p   = (const float*)d_in[6];
    const int*   idx = (const int*)d_in[7];
    float* out = (float*)d_out;

    const int n = in_sizes[0] / D;   // 500000

    seg_offsets_kernel<<<(n + 255) / 256, 256>>>(idx, n);
    pool_kernel<<<(SS + 7) / 8, 256>>>(x, w, Wg, bg, p);
    gemm_kernel<<<dim3(D / GBN, (SS + GBM - 1) / GBM), 256>>>(Wm, bm, out);
}

// round 11
// speedup vs baseline: 1.7392x; 1.0085x over previous
#include <cuda_runtime.h>
#include <cuda_bf16.h>
#include <cstdint>

#define D 256
#define SS 20000

// ---- scratch (device globals; allocation is forbidden) ----
__device__ float g_pooled[(size_t)SS * D];   // 20.48 MB
__device__ float g_gsum[SS];
__device__ int   g_segstart[SS + 1];

// ---------------------------------------------------------------------------
// Kernel 1: segment offsets from sorted index. seg_start[s] = lower_bound(index, s)
// ---------------------------------------------------------------------------
__global__ void seg_offsets_kernel(const int* __restrict__ index, int n) {
    int i = blockIdx.x * blockDim.x + threadIdx.x;
    if (i >= n) return;
    int cur = index[i];
    if (i == 0) {
        for (int s = 0; s <= cur; ++s) g_segstart[s] = 0;
    } else {
        int prev = index[i - 1];
        if (prev != cur)
            for (int s = prev + 1; s <= cur; ++s) g_segstart[s] = i;
    }
    if (i == n - 1) {
        for (int s = cur + 1; s <= SS; ++s) g_segstart[s] = n;
    }
}

// ---------------------------------------------------------------------------
// Kernel 2: warp-per-segment online-softmax pooling, PAIRED rows.
// Lane l owns feature columns [8l, 8l+8). Per iteration: two rows in flight
// (2KB/warp MLP), two interleaved butterfly reductions, one online-rescale
// per pair. Barrier-free, smem-free. Single pass over x -> HBM-bound.
// ---------------------------------------------------------------------------
__global__ void __launch_bounds__(256) pool_kernel(
    const float* __restrict__ x, const float* __restrict__ w,
    const float* __restrict__ Wg, const float* __restrict__ bg,
    const float* __restrict__ p)
{
    const int warp = threadIdx.x >> 5, lane = threadIdx.x & 31;
    const int s = blockIdx.x * 8 + warp;
    if (s >= SS) return;

    const int lo  = g_segstart[s];
    const int cnt = g_segstart[s + 1] - lo;

    float* outp = g_pooled + (size_t)s * D + lane * 8;

    if (cnt == 0) {
        float4 z = make_float4(0.f, 0.f, 0.f, 0.f);
        *reinterpret_cast<float4*>(outp)     = z;
        *reinterpret_cast<float4*>(outp + 4) = z;
        if (lane == 0) g_gsum[s] = 0.f;
        return;
    }

    // Wg slice for this lane's 8 columns
    const float4 wg0 = *reinterpret_cast<const float4*>(Wg + lane * 8);
    const float4 wg1 = *reinterpret_cast<const float4*>(Wg + lane * 8 + 4);
    const float bgv = bg[0];
    const float pv  = p[0];

    float m = -3.4e38f, dnm = 0.f;
    float acc[8] = {0.f, 0.f, 0.f, 0.f, 0.f, 0.f, 0.f, 0.f};

    const float* base = x + (size_t)lo * D + lane * 8;
    const int last = cnt - 1;

    // ---- prefetch pair 0 (row indices clamped to segment; always safe) ----
    int ra = 0, rb = (1 <= last) ? 1 : last;
    float4 a0 = *reinterpret_cast<const float4*>(base + (size_t)ra * D);
    float4 a1 = *reinterpret_cast<const float4*>(base + (size_t)ra * D + 4);
    float4 b0 = *reinterpret_cast<const float4*>(base + (size_t)rb * D);
    float4 b1 = *reinterpret_cast<const float4*>(base + (size_t)rb * D + 4);
    float  wa = w[lo + ra];
    float  wb = w[lo + rb];

    for (int r = 0; r < cnt; r += 2) {
        // ---- prefetch next pair (clamped; overlaps with compute below) ----
        float4 pa0 = a0, pa1 = a1, pb0 = b0, pb1 = b1;
        float  pwa = wa, pwb = wb;
        if (r + 2 < cnt) {
            const int na = r + 2;
            const int nb = (r + 3 <= last) ? r + 3 : last;
            pa0 = *reinterpret_cast<const float4*>(base + (size_t)na * D);
            pa1 = *reinterpret_cast<const float4*>(base + (size_t)na * D + 4);
            pb0 = *reinterpret_cast<const float4*>(base + (size_t)nb * D);
            pb1 = *reinterpret_cast<const float4*>(base + (size_t)nb * D + 4);
            pwa = w[lo + na];
            pwb = w[lo + nb];
        }

        // ---- two partial dots (independent -> ILP) ----
        float ta, tb;
        ta = a0.x * wg0.x;                 tb = b0.x * wg0.x;
        ta = fmaf(a0.y, wg0.y, ta);        tb = fmaf(b0.y, wg0.y, tb);
        ta = fmaf(a0.z, wg0.z, ta);        tb = fmaf(b0.z, wg0.z, tb);
        ta = fmaf(a0.w, wg0.w, ta);        tb = fmaf(b0.w, wg0.w, tb);
        ta = fmaf(a1.x, wg1.x, ta);        tb = fmaf(b1.x, wg1.x, tb);
        ta = fmaf(a1.y, wg1.y, ta);        tb = fmaf(b1.y, wg1.y, tb);
        ta = fmaf(a1.z, wg1.z, ta);        tb = fmaf(b1.z, wg1.z, tb);
        ta = fmaf(a1.w, wg1.w, ta);        tb = fmaf(b1.w, wg1.w, tb);

        // ---- interleaved butterflies (two independent shfl chains) ----
        #pragma unroll
        for (int o = 16; o; o >>= 1) {
            ta += __shfl_xor_sync(0xffffffffu, ta, o);
            tb += __shfl_xor_sync(0xffffffffu, tb, o);
        }
        const float ga = ta + bgv;
        const float gb = tb + bgv;
        const bool  vb = (r + 1 < cnt);

        // ---- online softmax update, one rescale per pair ----
        float mn = fmaxf(m, ga);
        if (vb) mn = fmaxf(mn, gb);
        const float scale = __expf(m - mn);
        const float ea = __expf(fmaf(pv, __logf(wa), ga - mn));
        const float eb = vb ? __expf(fmaf(pv, __logf(wb), gb - mn)) : 0.f;
        dnm = fmaf(dnm, scale, ea + eb);
        acc[0] = fmaf(eb, b0.x, fmaf(acc[0], scale, ea * a0.x));
        acc[1] = fmaf(eb, b0.y, fmaf(acc[1], scale, ea * a0.y));
        acc[2] = fmaf(eb, b0.z, fmaf(acc[2], scale, ea * a0.z));
        acc[3] = fmaf(eb, b0.w, fmaf(acc[3], scale, ea * a0.w));
        acc[4] = fmaf(eb, b1.x, fmaf(acc[4], scale, ea * a1.x));
        acc[5] = fmaf(eb, b1.y, fmaf(acc[5], scale, ea * a1.y));
        acc[6] = fmaf(eb, b1.z, fmaf(acc[6], scale, ea * a1.z));
        acc[7] = fmaf(eb, b1.w, fmaf(acc[7], scale, ea * a1.w));
        m = mn;

        a0 = pa0; a1 = pa1; b0 = pb0; b1 = pb1; wa = pwa; wb = pwb;
    }

    const float inv = 1.f / (dnm + 1e-10f);
    float4 o0, o1;
    o0.x = acc[0] * inv; o0.y = acc[1] * inv; o0.z = acc[2] * inv; o0.w = acc[3] * inv;
    o1.x = acc[4] * inv; o1.y = acc[5] * inv; o1.z = acc[6] * inv; o1.w = acc[7] * inv;
    *reinterpret_cast<float4*>(outp)     = o0;
    *reinterpret_cast<float4*>(outp + 4) = o1;
    if (lane == 0) g_gsum[s] = dnm * inv;   // sum of normalized gates
}

// ---------------------------------------------------------------------------
// Kernel 3: out = pooled @ Wm + gsum[:,None]*bm[None,:]   (M=20000, N=256, K=256)
// 128x128 block tile, BK=8, 8x8 micro-tile with PACKED fma.rn.f32x2
// (2x fp32 MAC throughput vs scalar FFMA), double-buffered smem.
// ---------------------------------------------------------------------------
#define GBM 128
#define GBN 128
#define GBK 8

#define FMA_F32X2(acc, a, b) \
    asm("fma.rn.f32x2 %0, %1, %2, %3;" : "=l"(acc) : "l"(a), "l"(b), "l"(acc))
#define PACK_DUP_F32X2(out, v) \
    asm("mov.b64 %0, {%1, %1};" : "=l"(out) : "r"(__float_as_uint(v)))
#define UNPACK_F32X2(lo, hi, in) \
    asm("mov.b64 {%0, %1}, %2;" : "=r"(lo), "=r"(hi) : "l"(in))

__global__ void __launch_bounds__(256) gemm_kernel(
    const float* __restrict__ Wm, const float* __restrict__ bm,
    float* __restrict__ out)
{
    __shared__ float As[2][GBK][GBM];
    __shared__ float Bs[2][GBK][GBN];

    const int m0 = blockIdx.y * GBM;
    const int n0 = blockIdx.x * GBN;
    const int t  = threadIdx.x;

    // global->smem load mapping
    const int a_row = t >> 1;          // 0..127
    const int a_k   = (t & 1) * 4;     // 0 or 4
    const int b_k   = t >> 5;          // 0..7
    const int b_n   = (t & 31) * 4;    // 0..124

    // compute mapping: 16x16 threads, each 8x8
    const int tx = t & 15;
    const int ty = t >> 4;

    // accumulators: 8 rows x 4 packed f32x2 pairs (= 8x8 floats)
    unsigned long long acc2[8][4];
    #pragma unroll
    for (int i = 0; i < 8; ++i)
        #pragma unroll
        for (int j = 0; j < 4; ++j) acc2[i][j] = 0ull;

    // ---- prologue: load tile 0 ----
    {
        const int gm = m0 + a_row;
        float4 av = make_float4(0.f, 0.f, 0.f, 0.f);
        if (gm < SS)
            av = *reinterpret_cast<const float4*>(&g_pooled[(size_t)gm * D + a_k]);
        As[0][a_k + 0][a_row] = av.x;
        As[0][a_k + 1][a_row] = av.y;
        As[0][a_k + 2][a_row] = av.z;
        As[0][a_k + 3][a_row] = av.w;
        const float4 bv = *reinterpret_cast<const float4*>(
            &Wm[(size_t)b_k * D + n0 + b_n]);
        *reinterpret_cast<float4*>(&Bs[0][b_k][b_n]) = bv;
    }
    __syncthreads();

    int buf = 0;
    for (int k0 = 0; k0 < D; k0 += GBK) {
        // ---- register prefetch of next tile (overlaps with compute) ----
        float4 av = make_float4(0.f, 0.f, 0.f, 0.f), bv;
        const bool has_next = (k0 + GBK) < D;
        if (has_next) {
            const int gm = m0 + a_row;
            if (gm < SS)
                av = *reinterpret_cast<const float4*>(
                    &g_pooled[(size_t)gm * D + k0 + GBK + a_k]);
            bv = *reinterpret_cast<const float4*>(
                &Wm[(size_t)(k0 + GBK + b_k) * D + n0 + b_n]);
        }

        // ---- compute on current buffer (packed f32x2) ----
        #pragma unroll
        for (int k = 0; k < GBK; ++k) {
            float a[8];
            *reinterpret_cast<float4*>(&a[0]) =
                *reinterpret_cast<const float4*>(&As[buf][k][ty * 8]);
            *reinterpret_cast<float4*>(&a[4]) =
                *reinterpret_cast<const float4*>(&As[buf][k][ty * 8 + 4]);
            ulonglong2 bv0 = *reinterpret_cast<const ulonglong2*>(&Bs[buf][k][tx * 8]);
            ulonglong2 bv1 = *reinterpret_cast<const ulonglong2*>(&Bs[buf][k][tx * 8 + 4]);
            unsigned long long b2[4] = {bv0.x, bv0.y, bv1.x, bv1.y};

            unsigned long long a2[8];
            #pragma unroll
            for (int i = 0; i < 8; ++i) PACK_DUP_F32X2(a2[i], a[i]);

            #pragma unroll
            for (int i = 0; i < 8; ++i)
                #pragma unroll
                for (int j = 0; j < 4; ++j)
                    FMA_F32X2(acc2[i][j], a2[i], b2[j]);
        }

        if (has_next) {
            const int nb = buf ^ 1;
            As[nb][a_k + 0][a_row] = av.x;
            As[nb][a_k + 1][a_row] = av.y;
            As[nb][a_k + 2][a_row] = av.z;
            As[nb][a_k + 3][a_row] = av.w;
            *reinterpret_cast<float4*>(&Bs[nb][b_k][b_n]) = bv;
            __syncthreads();
            buf = nb;
        }
    }

    // ---- epilogue: + gsum[m]*bm[n], vectorized stores ----
    float bmr[8];
    *reinterpret_cast<float4*>(&bmr[0]) =
        *reinterpret_cast<const float4*>(&bm[n0 + tx * 8]);
    *reinterpret_cast<float4*>(&bmr[4]) =
        *reinterpret_cast<const float4*>(&bm[n0 + tx * 8 + 4]);

    #pragma unroll
    for (int i = 0; i < 8; ++i) {
        const int m = m0 + ty * 8 + i;
        if (m >= SS) break;
        const float gs = g_gsum[m];
        float accf[8];
        #pragma unroll
        for (int j = 0; j < 4; ++j) {
            unsigned int lo, hi;
            UNPACK_F32X2(lo, hi, acc2[i][j]);
            accf[2 * j]     = __uint_as_float(lo);
            accf[2 * j + 1] = __uint_as_float(hi);
        }
        float4 o0, o1;
        o0.x = fmaf(gs, bmr[0], accf[0]);
        o0.y = fmaf(gs, bmr[1], accf[1]);
        o0.z = fmaf(gs, bmr[2], accf[2]);
        o0.w = fmaf(gs, bmr[3], accf[3]);
        o1.x = fmaf(gs, bmr[4], accf[4]);
        o1.y = fmaf(gs, bmr[5], accf[5]);
        o1.z = fmaf(gs, bmr[6], accf[6]);
        o1.w = fmaf(gs, bmr[7], accf[7]);
        *reinterpret_cast<float4*>(&out[(size_t)m * D + n0 + tx * 8])     = o0;
        *reinterpret_cast<float4*>(&out[(size_t)m * D + n0 + tx * 8 + 4]) = o1;
    }
}

// ---------------------------------------------------------------------------
extern "C" void kernel_launch(void* const* d_in, const int* in_sizes, int n_in,
                              void* d_out, int out_size)
{
    const float* x   = (const float*)d_in[0];
    const float* w   = (const float*)d_in[1];
    const float* Wg  = (const float*)d_in[2];
    const float* bg  = (const float*)d_in[3];
    const float* Wm  = (const float*)d_in[4];
    const float* bm  = (const float*)d_in[5];
    const float* p   = (const float*)d_in[6];
    const int*   idx = (const int*)d_in[7];
    float* out = (float*)d_out;

    const int n = in_sizes[0] / D;   // 500000

    seg_offsets_kernel<<<(n + 255) / 256, 256>>>(idx, n);
    pool_kernel<<<(SS + 7) / 8, 256>>>(x, w, Wg, bg, p);
    gemm_kernel<<<dim3(D / GBN, (SS + GBM - 1) / GBM), 256>>>(Wm, bm, out);
}

// round 15
// speedup vs baseline: 1.8622x; 1.0707x over previous
#include <cuda_runtime.h>
#include <cuda_bf16.h>
#include <cstdint>

#define D 256
#define SS 20000
#define DEPTH 8          // cp.async prefetch distance (rows in flight per warp)
#define RING  9          // ring slots = DEPTH+1 (one-slot slack vs overwrite)

// ---- scratch (device globals; allocation is forbidden) ----
__device__ float g_pooled[(size_t)SS * D];   // 20.48 MB
__device__ float g_gsum[SS];
__device__ int   g_segstart[SS + 1];

// ---------------------------------------------------------------------------
// Kernel 1: segment offsets from sorted index.
// ---------------------------------------------------------------------------
__global__ void seg_offsets_kernel(const int* __restrict__ index, int n) {
    int i = blockIdx.x * blockDim.x + threadIdx.x;
    if (i >= n) return;
    int cur = index[i];
    if (i == 0) {
        for (int s = 0; s <= cur; ++s) g_segstart[s] = 0;
    } else {
        int prev = index[i - 1];
        if (prev != cur)
            for (int s = prev + 1; s <= cur; ++s) g_segstart[s] = i;
    }
    if (i == n - 1) {
        for (int s = cur + 1; s <= SS; ++s) g_segstart[s] = n;
    }
}

// ---------------------------------------------------------------------------
// Kernel 2: warp-per-segment online-softmax pooling with cp.async row ring.
// Each warp owns a segment; a 9-slot x 1KB smem ring holds 8 rows in flight
// (LDGSTS -> no register cost), XOR-swizzled for conflict-free 32B/lane
// access. Lane l copies and reads exactly bytes [32l,32l+32) of each row, so
// cp.async.wait_group alone orders producer->consumer (no barriers at all).
// ---------------------------------------------------------------------------
__global__ void __launch_bounds__(256) pool_kernel(
    const float* __restrict__ x, const float* __restrict__ w,
    const float* __restrict__ Wg, const float* __restrict__ bg,
    const float* __restrict__ p)
{
    extern __shared__ char smem_raw[];   // 8 warps * RING * 1024 B
    const int warp = threadIdx.x >> 5, lane = threadIdx.x & 31;
    const int s = blockIdx.x * 8 + warp;
    if (s >= SS) return;

    const int lo  = g_segstart[s];
    const int cnt = g_segstart[s + 1] - lo;
    float* outp = g_pooled + (size_t)s * D + lane * 8;

    if (cnt == 0) {
        float4 z = make_float4(0.f, 0.f, 0.f, 0.f);
        *reinterpret_cast<float4*>(outp)     = z;
        *reinterpret_cast<float4*>(outp + 4) = z;
        if (lane == 0) g_gsum[s] = 0.f;
        return;
    }

    uint32_t sbase;
    asm("{ .reg .u64 t; cvta.to.shared.u64 t, %1; cvt.u32.u64 %0, t; }"
        : "=r"(sbase) : "l"(smem_raw));
    sbase += warp * (RING * 1024);

    // XOR swizzle within a 1KB row slot: conflict-free for 32B/lane ld/st
    const uint32_t bl = lane * 32u;
    const uint32_t bh = bl + 16u;
    const uint32_t off_lo = bl ^ (((bl >> 7) & 1u) << 4);
    const uint32_t off_hi = bh ^ (((bh >> 7) & 1u) << 4);

    const char* src_base = reinterpret_cast<const char*>(x)
                         + (size_t)lo * 1024 + lane * 32;
    const int last = cnt - 1;

    // ---- prologue: DEPTH non-empty groups (row index clamped at tail) ----
    #pragma unroll
    for (int j = 0; j < DEPTH; ++j) {
        const int jj = (j <= last) ? j : last;
        const uint32_t dst = sbase + j * 1024;
        const char* src = src_base + (size_t)jj * 1024;
        asm volatile(
            "cp.async.cg.shared.global [%0], [%2], 16;\n\t"
            "cp.async.cg.shared.global [%1], [%3], 16;\n\t"
            "cp.async.commit_group;\n\t"
            :: "r"(dst + off_lo), "r"(dst + off_hi), "l"(src), "l"(src + 16));
    }

    const float4 wg0 = *reinterpret_cast<const float4*>(Wg + lane * 8);
    const float4 wg1 = *reinterpret_cast<const float4*>(Wg + lane * 8 + 4);
    const float bgv = bg[0];
    const float pv  = p[0];

    float m = -3.4e38f, dnm = 0.f;
    float acc[8] = {0.f, 0.f, 0.f, 0.f, 0.f, 0.f, 0.f, 0.f};
    float wc = w[lo];

    int slot_r = 0, slot_i = DEPTH;
    for (int r = 0; r < cnt; ++r) {
        const float wn = (r < last) ? w[lo + r + 1] : wc;   // mostly L1-hit

        // row r's group (the (r+1)-th committed) is complete after this
        asm volatile("cp.async.wait_group 7;" ::: "memory");

        const uint32_t sa = sbase + slot_r * 1024;
        float4 c0, c1;
        asm volatile("ld.shared.v4.f32 {%0,%1,%2,%3}, [%4];"
            : "=f"(c0.x), "=f"(c0.y), "=f"(c0.z), "=f"(c0.w)
            : "r"(sa + off_lo));
        asm volatile("ld.shared.v4.f32 {%0,%1,%2,%3}, [%4];"
            : "=f"(c1.x), "=f"(c1.y), "=f"(c1.z), "=f"(c1.w)
            : "r"(sa + off_hi));

        // ---- issue row r+DEPTH into slot_i (overwrites row r-1's slot) ----
        {
            const int j  = r + DEPTH;
            const int jj = (j <= last) ? j : last;    // clamp: group never empty
            const uint32_t dst = sbase + slot_i * 1024;
            const char* src = src_base + (size_t)jj * 1024;
            asm volatile(
                "cp.async.cg.shared.global [%0], [%2], 16;\n\t"
                "cp.async.cg.shared.global [%1], [%3], 16;\n\t"
                "cp.async.commit_group;\n\t"
                :: "r"(dst + off_lo), "r"(dst + off_hi), "l"(src), "l"(src + 16));
        }

        // ---- partial dot over this lane's 8 columns ----
        float t;
        t = c0.x * wg0.x;
        t = fmaf(c0.y, wg0.y, t);
        t = fmaf(c0.z, wg0.z, t);
        t = fmaf(c0.w, wg0.w, t);
        t = fmaf(c1.x, wg1.x, t);
        t = fmaf(c1.y, wg1.y, t);
        t = fmaf(c1.z, wg1.z, t);
        t = fmaf(c1.w, wg1.w, t);
        #pragma unroll
        for (int o = 16; o; o >>= 1) t += __shfl_xor_sync(0xffffffffu, t, o);
        const float g = t + bgv;

        // ---- online softmax update ----
        const float mn    = fmaxf(m, g);
        const float scale = __expf(m - mn);
        const float e     = __expf(fmaf(pv, __logf(wc), g - mn));
        dnm = fmaf(dnm, scale, e);
        acc[0] = fmaf(acc[0], scale, e * c0.x);
        acc[1] = fmaf(acc[1], scale, e * c0.y);
        acc[2] = fmaf(acc[2], scale, e * c0.z);
        acc[3] = fmaf(acc[3], scale, e * c0.w);
        acc[4] = fmaf(acc[4], scale, e * c1.x);
        acc[5] = fmaf(acc[5], scale, e * c1.y);
        acc[6] = fmaf(acc[6], scale, e * c1.z);
        acc[7] = fmaf(acc[7], scale, e * c1.w);
        m  = mn;
        wc = wn;

        if (++slot_r == RING) slot_r = 0;
        if (++slot_i == RING) slot_i = 0;
    }

    const float inv = 1.f / (dnm + 1e-10f);
    float4 o0, o1;
    o0.x = acc[0] * inv; o0.y = acc[1] * inv; o0.z = acc[2] * inv; o0.w = acc[3] * inv;
    o1.x = acc[4] * inv; o1.y = acc[5] * inv; o1.z = acc[6] * inv; o1.w = acc[7] * inv;
    *reinterpret_cast<float4*>(outp)     = o0;
    *reinterpret_cast<float4*>(outp + 4) = o1;
    if (lane == 0) g_gsum[s] = dnm * inv;
}

// ---------------------------------------------------------------------------
// Kernel 3: out = pooled @ Wm + gsum[:,None]*bm[None,:]   (M=20000, N=256, K=256)
// 128x128 tile, BK=8, 8x8 micro-tile as two stride-4 column groups
// (tx*4 and 64+tx*4) -> conflict-free LDS.128. Packed fma.rn.f32x2.
// ---------------------------------------------------------------------------
#define GBM 128
#define GBN 128
#define GBK 8

#define FMA_F32X2(acc, a, b) \
    asm("fma.rn.f32x2 %0, %1, %2, %3;" : "=l"(acc) : "l"(a), "l"(b), "l"(acc))
#define PACK_DUP_F32X2(out, v) \
    asm("mov.b64 %0, {%1, %1};" : "=l"(out) : "r"(__float_as_uint(v)))
#define UNPACK_F32X2(lo, hi, in) \
    asm("mov.b64 {%0, %1}, %2;" : "=r"(lo), "=r"(hi) : "l"(in))

__global__ void __launch_bounds__(256) gemm_kernel(
    const float* __restrict__ Wm, const float* __restrict__ bm,
    float* __restrict__ out)
{
    __shared__ float As[2][GBK][GBM];
    __shared__ float Bs[2][GBK][GBN];

    const int m0 = blockIdx.y * GBM;
    const int n0 = blockIdx.x * GBN;
    const int t  = threadIdx.x;

    // global->smem load mapping
    const int a_row = t >> 1;          // 0..127
    const int a_k   = (t & 1) * 4;     // 0 or 4
    const int b_k   = t >> 5;          // 0..7
    const int b_n   = (t & 31) * 4;    // 0..124

    // compute mapping: 16x16 threads; each owns rows ty*8+ [0,8) and
    // column groups [tx*4, tx*4+4) and [64+tx*4, 64+tx*4+4)
    const int tx = t & 15;
    const int ty = t >> 4;

    // accumulators: 8 rows x 4 packed f32x2 (j=0,1 -> low group; 2,3 -> high)
    unsigned long long acc2[8][4];
    #pragma unroll
    for (int i = 0; i < 8; ++i)
        #pragma unroll
        for (int j = 0; j < 4; ++j) acc2[i][j] = 0ull;

    // ---- prologue: load tile 0 ----
    {
        const int gm = m0 + a_row;
        float4 av = make_float4(0.f, 0.f, 0.f, 0.f);
        if (gm < SS)
            av = *reinterpret_cast<const float4*>(&g_pooled[(size_t)gm * D + a_k]);
        As[0][a_k + 0][a_row] = av.x;
        As[0][a_k + 1][a_row] = av.y;
        As[0][a_k + 2][a_row] = av.z;
        As[0][a_k + 3][a_row] = av.w;
        const float4 bv = *reinterpret_cast<const float4*>(
            &Wm[(size_t)b_k * D + n0 + b_n]);
        *reinterpret_cast<float4*>(&Bs[0][b_k][b_n]) = bv;
    }
    __syncthreads();

    int buf = 0;
    for (int k0 = 0; k0 < D; k0 += GBK) {
        // ---- register prefetch of next tile ----
        float4 av = make_float4(0.f, 0.f, 0.f, 0.f), bv;
        const bool has_next = (k0 + GBK) < D;
        if (has_next) {
            const int gm = m0 + a_row;
            if (gm < SS)
                av = *reinterpret_cast<const float4*>(
                    &g_pooled[(size_t)gm * D + k0 + GBK + a_k]);
            bv = *reinterpret_cast<const float4*>(
                &Wm[(size_t)(k0 + GBK + b_k) * D + n0 + b_n]);
        }

        // ---- compute (packed f32x2; conflict-free B loads) ----
        #pragma unroll
        for (int k = 0; k < GBK; ++k) {
            float a[8];
            *reinterpret_cast<float4*>(&a[0]) =
                *reinterpret_cast<const float4*>(&As[buf][k][ty * 8]);
            *reinterpret_cast<float4*>(&a[4]) =
                *reinterpret_cast<const float4*>(&As[buf][k][ty * 8 + 4]);
            const ulonglong2 blo = *reinterpret_cast<const ulonglong2*>(
                &Bs[buf][k][tx * 4]);
            const ulonglong2 bhi = *reinterpret_cast<const ulonglong2*>(
                &Bs[buf][k][64 + tx * 4]);
            unsigned long long b2[4] = {blo.x, blo.y, bhi.x, bhi.y};

            unsigned long long a2[8];
            #pragma unroll
            for (int i = 0; i < 8; ++i) PACK_DUP_F32X2(a2[i], a[i]);

            #pragma unroll
            for (int i = 0; i < 8; ++i)
                #pragma unroll
                for (int j = 0; j < 4; ++j)
                    FMA_F32X2(acc2[i][j], a2[i], b2[j]);
        }

        if (has_next) {
            const int nb = buf ^ 1;
            As[nb][a_k + 0][a_row] = av.x;
            As[nb][a_k + 1][a_row] = av.y;
            As[nb][a_k + 2][a_row] = av.z;
            As[nb][a_k + 3][a_row] = av.w;
            *reinterpret_cast<float4*>(&Bs[nb][b_k][b_n]) = bv;
            __syncthreads();
            buf = nb;
        }
    }

    // ---- epilogue: + gsum[m]*bm[n] over the two column groups ----
    const float4 bm_lo = *reinterpret_cast<const float4*>(&bm[n0 + tx * 4]);
    const float4 bm_hi = *reinterpret_cast<const float4*>(&bm[n0 + 64 + tx * 4]);

    #pragma unroll
    for (int i = 0; i < 8; ++i) {
        const int m = m0 + ty * 8 + i;
        if (m >= SS) break;
        const float gs = g_gsum[m];
        float f[8];
        #pragma unroll
        for (int j = 0; j < 4; ++j) {
            unsigned int lo, hi;
            UNPACK_F32X2(lo, hi, acc2[i][j]);
            f[2 * j]     = __uint_as_float(lo);
            f[2 * j + 1] = __uint_as_float(hi);
        }
        float4 o0, o1;
        o0.x = fmaf(gs, bm_lo.x, f[0]);
        o0.y = fmaf(gs, bm_lo.y, f[1]);
        o0.z = fmaf(gs, bm_lo.z, f[2]);
        o0.w = fmaf(gs, bm_lo.w, f[3]);
        o1.x = fmaf(gs, bm_hi.x, f[4]);
        o1.y = fmaf(gs, bm_hi.y, f[5]);
        o1.z = fmaf(gs, bm_hi.z, f[6]);
        o1.w = fmaf(gs, bm_hi.w, f[7]);
        *reinterpret_cast<float4*>(&out[(size_t)m * D + n0 + tx * 4])      = o0;
        *reinterpret_cast<float4*>(&out[(size_t)m * D + n0 + 64 + tx * 4]) = o1;
    }
}

// ---------------------------------------------------------------------------
extern "C" void kernel_launch(void* const* d_in, const int* in_sizes, int n_in,
                              void* d_out, int out_size)
{
    const float* x   = (const float*)d_in[0];
    const float* w   = (const float*)d_in[1];
    const float* Wg  = (const float*)d_in[2];
    const float* bg  = (const float*)d_in[3];
    const float* Wm  = (const float*)d_in[4];
    const float* bm  = (const float*)d_in[5];
    const float* p   = (const float*)d_in[6];
    const int*   idx = (const int*)d_in[7];
    float* out = (float*)d_out;

    const int n = in_sizes[0] / D;   // 500000

    const int pool_smem = 8 * RING * 1024;   // 72 KB -> 3 CTAs/SM
    cudaFuncSetAttribute(pool_kernel, cudaFuncAttributeMaxDynamicSharedMemorySize,
                         pool_smem);

    seg_offsets_kernel<<<(n + 255) / 256, 256>>>(idx, n);
    pool_kernel<<<(SS + 7) / 8, 256, pool_smem>>>(x, w, Wg, bg, p);
    gemm_kernel<<<dim3(D / GBN, (SS + GBM - 1) / GBM), 256>>>(Wm, bm, out);
}